// round 3
// baseline (speedup 1.0000x reference)
#include <cuda_runtime.h>

#define BATCH 1024
#define SEQ   512
#define MTOT  (BATCH * SEQ)   // 524288

// ---------------- scratch (static device arrays; no allocations) ----------------
__device__ float g_x1f[MTOT * 100];   // layer1 fwd output (B,S,100)
__device__ float g_x1b[MTOT * 100];   // layer1 bwd output
__device__ float g_gif[MTOT * 150];   // gi scratch fwd (reused L2 then L3)
__device__ float g_gib[MTOT * 150];   // gi scratch bwd
__device__ float g_x2f[MTOT * 50];    // layer2 fwd output
__device__ float g_x2b[MTOT * 50];    // layer2 bwd output

// ---------------- packed f32x2 helpers (FFMA2: 2 fp32 MACs per instruction) ------
__device__ __forceinline__ unsigned long long pack2(float lo, float hi) {
    unsigned long long r;
    asm("mov.b64 %0, {%1, %2};" : "=l"(r) : "f"(lo), "f"(hi));
    return r;
}
__device__ __forceinline__ float2 unpack2(unsigned long long v) {
    float2 r;
    asm("mov.b64 {%0, %1}, %2;" : "=f"(r.x), "=f"(r.y) : "l"(v));
    return r;
}
__device__ __forceinline__ void fma2(unsigned long long &acc,
                                     unsigned long long a, unsigned long long b) {
    asm("fma.rn.f32x2 %0, %1, %2, %0;" : "+l"(acc) : "l"(a), "l"(b));
}

// ---------------- fast activations ----------------
__device__ __forceinline__ float sigf(float x) {
    return __fdividef(1.0f, 1.0f + __expf(-x));
}
__device__ __forceinline__ float tanh_fast(float x) {
    return 2.0f * __fdividef(1.0f, 1.0f + __expf(-2.0f * x)) - 1.0f;
}

// =================================================================================
// Layer 1 recurrence (dilation 1). 148 blocks (74 fwd + 74 bwd), 14 chains/block,
// 1 block/SM. GEMM phase: 300 threads, thread = (column-pair p, chain-group g of 7),
// packed FFMA2 with duplicated-H smem (HD[c][k] = (h,h)) and pre-paired weights
// WP4[k2][p] = (W[2k2][2p],W[2k2][2p+1],W[2k2+1][2p],W[2k2+1][2p+1]),
// W[k][j] = whh[j*100+k]. Per thread/step: 700 FFMA2 + 400 LDS.128.
// =================================================================================
#define R1_SM_WP   0               // 50*150*4 = 30000
#define R1_SM_WIH  30000
#define R1_SM_BIH  30300
#define R1_SM_BHH  30600
#define R1_SM_HD   30900           // 14*100*2 = 2800 (dup pairs); 16B aligned
#define R1_SM_GH   33700           // 14*300 = 4200
#define R1_SM_XD   37900           // 14*512 = 7168
#define R1_SM_FLOATS 45068
#define R1_SMEM_BYTES (R1_SM_FLOATS * 4)

__global__ void __launch_bounds__(320, 1) rec1_kernel(
    const float* __restrict__ data,
    const float* __restrict__ wih_f, const float* __restrict__ whh_f,
    const float* __restrict__ bih_f, const float* __restrict__ bhh_f,
    const float* __restrict__ wih_b, const float* __restrict__ whh_b,
    const float* __restrict__ bih_b, const float* __restrict__ bhh_b,
    float* __restrict__ x1f, float* __restrict__ x1b, float* __restrict__ out)
{
    extern __shared__ float sm[];
    const int tid = threadIdx.x;
    const int bid = blockIdx.x;
    const int dir = (bid >= 74) ? 1 : 0;
    const int cb  = (bid - dir * 74) * 14;

    const float* wih = dir ? wih_b : wih_f;
    const float* whh = dir ? whh_b : whh_f;
    const float* bih = dir ? bih_b : bih_f;
    const float* bhh = dir ? bhh_b : bhh_f;
    float* xout = dir ? x1b : x1f;
    const int outoff = dir ? 200 : 0;

    float* WP  = sm + R1_SM_WP;
    float* WIH = sm + R1_SM_WIH;
    float* BIH = sm + R1_SM_BIH;
    float* BHH = sm + R1_SM_BHH;
    float* HD  = sm + R1_SM_HD;
    float* GH  = sm + R1_SM_GH;
    float* XD  = sm + R1_SM_XD;

    // WP flat idx = k2*600 + p*4 + c4 ; k = 2*k2+(c4>>1), j = 2*p+(c4&1)
    for (int i = tid; i < 30000; i += 320) {
        const int c4 = i & 3;
        const int p  = (i >> 2) % 150;
        const int k2 = i / 600;
        const int k  = 2 * k2 + (c4 >> 1);
        const int j  = 2 * p + (c4 & 1);
        WP[i] = whh[j * 100 + k];
    }
    for (int i = tid; i < 300; i += 320) {
        WIH[i] = wih[i]; BIH[i] = bih[i]; BHH[i] = bhh[i];
    }
    for (int i = tid; i < 2800; i += 320) HD[i] = 0.0f;
    // stage input sequence (reversed for bwd direction)
    for (int i = tid; i < 14 * 512; i += 320) {
        int c = i >> 9, s = i & 511;
        int b = cb + c;
        XD[i] = (b < BATCH) ? data[b * 512 + (dir ? (511 - s) : s)] : 0.0f;
    }
    __syncthreads();

    for (int s = 0; s < 512; s++) {
        if (tid < 300) {
            const int p = tid % 150;
            const int g = tid / 150;
            unsigned long long acc2[7];
            const float2 bb = *reinterpret_cast<const float2*>(BHH + 2 * p);
            const unsigned long long binit = pack2(bb.x, bb.y);
            #pragma unroll
            for (int c = 0; c < 7; c++) acc2[c] = binit;
            #pragma unroll 5
            for (int k2 = 0; k2 < 50; k2++) {
                const ulonglong2 wv = *reinterpret_cast<const ulonglong2*>(WP + (k2 * 150 + p) * 4);
                #pragma unroll
                for (int c = 0; c < 7; c++) {
                    const ulonglong2 hv = *reinterpret_cast<const ulonglong2*>(HD + (g * 7 + c) * 200 + 4 * k2);
                    fma2(acc2[c], hv.x, wv.x);
                    fma2(acc2[c], hv.y, wv.y);
                }
            }
            #pragma unroll
            for (int c = 0; c < 7; c++) {
                *reinterpret_cast<float2*>(GH + (g * 7 + c) * 300 + 2 * p) = unpack2(acc2[c]);
            }
        }
        __syncthreads();

        for (int it = tid; it < 1400; it += 320) {
            const int c = it / 100;
            const int u = it - c * 100;
            const int b = cb + c;
            const float xv  = XD[c * 512 + s];
            const float ir  = fmaf(xv, WIH[u],       BIH[u]);
            const float iz  = fmaf(xv, WIH[100 + u], BIH[100 + u]);
            const float inn = fmaf(xv, WIH[200 + u], BIH[200 + u]);
            const float hr = GH[c * 300 + u];
            const float hz = GH[c * 300 + 100 + u];
            const float hn = GH[c * 300 + 200 + u];
            const float rg = sigf(ir + hr);
            const float zg = sigf(iz + hz);
            const float ng = tanh_fast(inn + rg * hn);
            const float hold = HD[(c * 100 + u) * 2];
            const float hnew = (1.0f - zg) * ng + zg * hold;
            *reinterpret_cast<float2*>(HD + (c * 100 + u) * 2) = make_float2(hnew, hnew);
            if (b < BATCH) {
                xout[(b * 512 + s) * 100 + u] = hnew;
                if (s == 511) out[b * 400 + outoff + u] = hnew;
            }
        }
        __syncthreads();
    }
}

// =================================================================================
// Input-projection GEMM: out[M,150] = x[M,K] @ w[150,K]^T + bias.  M = 524288,
// K in {100, 50}. Block tile 128 x 160, 256 threads, 8 rows x 5 col-pairs of
// packed FFMA2 per thread. SMEM: duplicated X (XDS[r][k] = (x,x)) and paired W
// (WPS[k2][pp] float4). K consumed in chunks of 50.
// =================================================================================
#define GM_SM_XDS 0        // 128*100 = 12800 (dup)
#define GM_SM_WPS 12800    // 25*80*4 = 8000
#define GM_SM_BS  20800    // 160
#define GM_SMEM_BYTES (20960 * 4)

__global__ void __launch_bounds__(256) gi_gemm_kernel(
    const float* __restrict__ x, const float* __restrict__ w,
    const float* __restrict__ bias, float* __restrict__ out, int K)
{
    extern __shared__ float sm[];
    float* XDS = sm + GM_SM_XDS;
    float* WPS = sm + GM_SM_WPS;
    float* BS  = sm + GM_SM_BS;
    const int tid = threadIdx.x;
    const int tx = tid & 15;
    const int ty = tid >> 4;
    const int m0 = blockIdx.x * 128;

    for (int i = tid; i < 160; i += 256) BS[i] = (i < 150) ? bias[i] : 0.0f;

    unsigned long long acc2[8][5];
    #pragma unroll
    for (int i = 0; i < 8; i++)
        #pragma unroll
        for (int j = 0; j < 5; j++) acc2[i][j] = 0ULL;

    const int nch = K / 50;
    for (int ch = 0; ch < nch; ch++) {
        const int k0 = ch * 50;
        __syncthreads();
        // X duplicated: XDS[r*100 + 2k + {0,1}] = x value
        for (int i = tid; i < 128 * 50; i += 256) {
            const int r = i / 50, k = i - r * 50;
            const float v = x[(m0 + r) * K + k0 + k];
            *reinterpret_cast<float2*>(XDS + r * 100 + 2 * k) = make_float2(v, v);
        }
        // W paired: WPS flat = k2*320 + pp*4 + c4 ; k = k0+2k2+(c4>>1), n = 2pp+(c4&1)
        for (int i = tid; i < 8000; i += 256) {
            const int c4 = i & 3;
            const int pp = (i >> 2) % 80;
            const int k2 = i / 320;
            const int k  = k0 + 2 * k2 + (c4 >> 1);
            const int n  = 2 * pp + (c4 & 1);
            WPS[i] = (n < 150) ? w[n * K + k] : 0.0f;
        }
        __syncthreads();
        for (int k2 = 0; k2 < 25; k2++) {
            ulonglong2 xx[8], ww[5];
            #pragma unroll
            for (int i = 0; i < 8; i++)
                xx[i] = *reinterpret_cast<const ulonglong2*>(XDS + (ty * 8 + i) * 100 + 4 * k2);
            #pragma unroll
            for (int j = 0; j < 5; j++)
                ww[j] = *reinterpret_cast<const ulonglong2*>(WPS + (k2 * 80 + tx + 16 * j) * 4);
            #pragma unroll
            for (int i = 0; i < 8; i++)
                #pragma unroll
                for (int j = 0; j < 5; j++) {
                    fma2(acc2[i][j], xx[i].x, ww[j].x);
                    fma2(acc2[i][j], xx[i].y, ww[j].y);
                }
        }
    }
    #pragma unroll
    for (int i = 0; i < 8; i++) {
        const int m = m0 + ty * 8 + i;
        #pragma unroll
        for (int j = 0; j < 5; j++) {
            const int pp = tx + 16 * j;
            if (pp < 75) {
                float2 v = unpack2(acc2[i][j]);
                v.x += BS[2 * pp];
                v.y += BS[2 * pp + 1];
                *reinterpret_cast<float2*>(out + m * 150 + 2 * pp) = v;
            }
        }
    }
}

// =================================================================================
// Layers 2/3 recurrence (H=50, gates=150, dilation 4 or 16). 28 chains/block,
// 160 threads, 2 blocks/SM. GEMM phase: 150 threads = 75 col-pairs x 2 chain-
// groups of 14, packed FFMA2 with duplicated-H smem + paired weights
// (W[k][j] = whh[j*50+k]). Per thread/step: 700 FFMA2 + 375 LDS.128.
// =================================================================================
#define R23_SM_WP  0       // 25*75*4 = 7500
#define R23_SM_BHH 7500    // 150 (+2 pad)
#define R23_SM_HD  7652    // 28*50*2 = 2800 (dup pairs); 16B aligned
#define R23_SM_GH  10452   // 28*150 = 4200
#define R23_SM_FLOATS 14652
#define R23_SMEM_BYTES (R23_SM_FLOATS * 4)

__global__ void __launch_bounds__(160, 2) rec23_kernel(
    const float* __restrict__ gi_f, const float* __restrict__ gi_b,
    const float* __restrict__ whh_fp, const float* __restrict__ bhh_fp,
    const float* __restrict__ whh_bp, const float* __restrict__ bhh_bp,
    float* __restrict__ xout_f, float* __restrict__ xout_b,
    float* __restrict__ out, int offF, int offB,
    int dil, int ds, int nc, int bpd, int ctot)
{
    extern __shared__ float sm[];
    float* WP  = sm + R23_SM_WP;
    float* BHH = sm + R23_SM_BHH;
    float* HD  = sm + R23_SM_HD;
    float* GH  = sm + R23_SM_GH;
    const int tid = threadIdx.x;
    const int bid = blockIdx.x;
    const int dir = (bid >= bpd) ? 1 : 0;
    const int chain0 = (bid - dir * bpd) * 28;
    const float* gi  = dir ? gi_b : gi_f;
    const float* whh = dir ? whh_bp : whh_fp;
    const float* bhh = dir ? bhh_bp : bhh_fp;
    float* xout = dir ? xout_b : xout_f;
    const int outoff = dir ? offB : offF;

    // WP flat = k2*300 + p*4 + c4 ; k = 2k2+(c4>>1), j = 2p+(c4&1)
    for (int i = tid; i < 7500; i += 160) {
        const int c4 = i & 3;
        const int p  = (i >> 2) % 75;
        const int k2 = i / 300;
        const int k  = 2 * k2 + (c4 >> 1);
        const int j  = 2 * p + (c4 & 1);
        WP[i] = whh[j * 50 + k];
    }
    for (int i = tid; i < 150; i += 160) BHH[i] = bhh[i];
    for (int i = tid; i < 2800; i += 160) HD[i] = 0.0f;
    __syncthreads();

    for (int step = 0; step < nc; step++) {
        if (tid < 150) {
            const int p = tid % 75;
            const int g = tid / 75;
            unsigned long long acc2[14];
            const float2 bb = *reinterpret_cast<const float2*>(BHH + 2 * p);
            const unsigned long long binit = pack2(bb.x, bb.y);
            #pragma unroll
            for (int c = 0; c < 14; c++) acc2[c] = binit;
            #pragma unroll 5
            for (int k2 = 0; k2 < 25; k2++) {
                const ulonglong2 wv = *reinterpret_cast<const ulonglong2*>(WP + (k2 * 75 + p) * 4);
                #pragma unroll
                for (int c = 0; c < 14; c++) {
                    const ulonglong2 hv = *reinterpret_cast<const ulonglong2*>(HD + (g * 14 + c) * 100 + 4 * k2);
                    fma2(acc2[c], hv.x, wv.x);
                    fma2(acc2[c], hv.y, wv.y);
                }
            }
            #pragma unroll
            for (int c = 0; c < 14; c++) {
                *reinterpret_cast<float2*>(GH + (g * 14 + c) * 150 + 2 * p) = unpack2(acc2[c]);
            }
        }
        __syncthreads();

        for (int it = tid; it < 28 * 50; it += 160) {
            const int c = it / 50;
            const int u = it - c * 50;
            const int chain = chain0 + c;
            if (chain < ctot) {
                const int b  = chain >> ds;
                const int rr = chain & (dil - 1);
                const int s  = (step << ds) + rr;
                const float* gp = gi + (b * 512 + s) * 150;
                const float ir  = gp[u];
                const float iz  = gp[50 + u];
                const float inn = gp[100 + u];
                const float hr = GH[c * 150 + u];
                const float hz = GH[c * 150 + 50 + u];
                const float hn = GH[c * 150 + 100 + u];
                const float rg = sigf(ir + hr);
                const float zg = sigf(iz + hz);
                const float ng = tanh_fast(inn + rg * hn);
                const float hold = HD[(c * 50 + u) * 2];
                const float hnew = (1.0f - zg) * ng + zg * hold;
                *reinterpret_cast<float2*>(HD + (c * 50 + u) * 2) = make_float2(hnew, hnew);
                if (xout) xout[(b * 512 + s) * 50 + u] = hnew;
                if (s == 511) out[b * 400 + outoff + u] = hnew;
            }
        }
        __syncthreads();
    }
}

// =================================================================================
// Host launcher
// =================================================================================
extern "C" void kernel_launch(void* const* d_in, const int* in_sizes, int n_in,
                              void* d_out, int out_size)
{
    const float* data = (const float*)d_in[0];
    // f1:1-4  f2:5-8  f3:9-12  b1:13-16  b2:17-20  b3:21-24 (wih, whh, bih, bhh)
    const float* f1_wih = (const float*)d_in[1];
    const float* f1_whh = (const float*)d_in[2];
    const float* f1_bih = (const float*)d_in[3];
    const float* f1_bhh = (const float*)d_in[4];
    const float* f2_wih = (const float*)d_in[5];
    const float* f2_whh = (const float*)d_in[6];
    const float* f2_bih = (const float*)d_in[7];
    const float* f2_bhh = (const float*)d_in[8];
    const float* f3_wih = (const float*)d_in[9];
    const float* f3_whh = (const float*)d_in[10];
    const float* f3_bih = (const float*)d_in[11];
    const float* f3_bhh = (const float*)d_in[12];
    const float* b1_wih = (const float*)d_in[13];
    const float* b1_whh = (const float*)d_in[14];
    const float* b1_bih = (const float*)d_in[15];
    const float* b1_bhh = (const float*)d_in[16];
    const float* b2_wih = (const float*)d_in[17];
    const float* b2_whh = (const float*)d_in[18];
    const float* b2_bih = (const float*)d_in[19];
    const float* b2_bhh = (const float*)d_in[20];
    const float* b3_wih = (const float*)d_in[21];
    const float* b3_whh = (const float*)d_in[22];
    const float* b3_bih = (const float*)d_in[23];
    const float* b3_bhh = (const float*)d_in[24];
    float* out = (float*)d_out;

    float *x1f, *x1b, *gif, *gib, *x2f, *x2b;
    cudaGetSymbolAddress((void**)&x1f, g_x1f);
    cudaGetSymbolAddress((void**)&x1b, g_x1b);
    cudaGetSymbolAddress((void**)&gif, g_gif);
    cudaGetSymbolAddress((void**)&gib, g_gib);
    cudaGetSymbolAddress((void**)&x2f, g_x2f);
    cudaGetSymbolAddress((void**)&x2b, g_x2b);

    cudaFuncSetAttribute(rec1_kernel,    cudaFuncAttributeMaxDynamicSharedMemorySize, R1_SMEM_BYTES);
    cudaFuncSetAttribute(gi_gemm_kernel, cudaFuncAttributeMaxDynamicSharedMemorySize, GM_SMEM_BYTES);
    cudaFuncSetAttribute(rec23_kernel,   cudaFuncAttributeMaxDynamicSharedMemorySize, R23_SMEM_BYTES);

    // Layer 1 (dil=1): both directions in one wave of 148 persistent blocks.
    rec1_kernel<<<148, 320, R1_SMEM_BYTES>>>(
        data, f1_wih, f1_whh, f1_bih, f1_bhh,
        b1_wih, b1_whh, b1_bih, b1_bhh, x1f, x1b, out);

    // Layer 2 input projections: gi = x1 @ wih^T + bih   (K = 100)
    gi_gemm_kernel<<<MTOT / 128, 256, GM_SMEM_BYTES>>>(x1f, f2_wih, f2_bih, gif, 100);
    gi_gemm_kernel<<<MTOT / 128, 256, GM_SMEM_BYTES>>>(x1b, b2_wih, b2_bih, gib, 100);

    // Layer 2 recurrence (dil=4): 4096 chains/dir, 28/block -> bpd 147, grid 294.
    rec23_kernel<<<294, 160, R23_SMEM_BYTES>>>(
        gif, gib, f2_whh, f2_bhh, b2_whh, b2_bhh,
        x2f, x2b, out, 100, 300, 4, 2, 128, 147, 4096);

    // Layer 3 input projections (K = 50), reusing gi scratch.
    gi_gemm_kernel<<<MTOT / 128, 256, GM_SMEM_BYTES>>>(x2f, f3_wih, f3_bih, gif, 50);
    gi_gemm_kernel<<<MTOT / 128, 256, GM_SMEM_BYTES>>>(x2b, b3_wih, b3_bih, gib, 50);

    // Layer 3 recurrence (dil=16): 16384 chains/dir, 28/block -> bpd 586, grid 1172.
    // Only the final hidden state is needed -> no x output buffer.
    rec23_kernel<<<1172, 160, R23_SMEM_BYTES>>>(
        gif, gib, f3_whh, f3_bhh, b3_whh, b3_bhh,
        nullptr, nullptr, out, 150, 350, 16, 4, 32, 586, 16384);

    (void)in_sizes; (void)n_in; (void)out_size;
}

// round 9
// speedup vs baseline: 1.1714x; 1.1714x over previous
#include <cuda_runtime.h>

#define BATCH 1024
#define SEQ   512
#define MTOT  (BATCH * SEQ)   // 524288

// ---------------- scratch (static device arrays; no allocations) ----------------
__device__ float g_x1f[MTOT * 100];   // layer1 fwd output (B,S,100)
__device__ float g_x1b[MTOT * 100];   // layer1 bwd output
__device__ float g_gif[MTOT * 150];   // gi scratch fwd (reused L2 then L3)
__device__ float g_gib[MTOT * 150];   // gi scratch bwd
__device__ float g_x2f[MTOT * 50];    // layer2 fwd output
__device__ float g_x2b[MTOT * 50];    // layer2 bwd output

// ---------------- packed f32x2 helpers (FFMA2: 2 fp32 MACs per instruction) ------
__device__ __forceinline__ unsigned long long pack2(float lo, float hi) {
    unsigned long long r;
    asm("mov.b64 %0, {%1, %2};" : "=l"(r) : "f"(lo), "f"(hi));
    return r;
}
__device__ __forceinline__ float2 unpack2(unsigned long long v) {
    float2 r;
    asm("mov.b64 {%0, %1}, %2;" : "=f"(r.x), "=f"(r.y) : "l"(v));
    return r;
}
__device__ __forceinline__ void fma2(unsigned long long &acc,
                                     unsigned long long a, unsigned long long b) {
    asm("fma.rn.f32x2 %0, %1, %2, %0;" : "+l"(acc) : "l"(a), "l"(b));
}

// ---------------- fast activations ----------------
__device__ __forceinline__ float sigf(float x) {
    return __fdividef(1.0f, 1.0f + __expf(-x));
}
__device__ __forceinline__ float tanh_fast(float x) {
    return 2.0f * __fdividef(1.0f, 1.0f + __expf(-2.0f * x)) - 1.0f;
}

// =================================================================================
// Layer 1 recurrence (dilation 1). 148 blocks (74 fwd + 74 bwd), 14 chains/block,
// 640 threads, 1 block/SM (smem 197KB) -> 20 warps/SM.
// GEMM phase: 600 threads = 150 col-pairs x 2 chain-groups(7) x 2 k-halves.
// Each computes FFMA2 partial sums over 25 k2; partials land in PG[ks][chain][300]
// and are combined (A+B) inside the activation phase (no extra barrier).
// =================================================================================
#define R1_WP   0          // 50*150*4 = 30000
#define R1_WIH  30000
#define R1_BIH  30304
#define R1_BHH  30608
#define R1_HD   30912      // 14*100*2 = 2800 dup pairs (16B aligned)
#define R1_PG   33712      // 2*14*300 = 8400 partial sums
#define R1_XD   42112      // 14*512 = 7168
#define R1_FLOATS 49280
#define R1_SMEM_BYTES (R1_FLOATS * 4)

__global__ void __launch_bounds__(640, 1) rec1_kernel(
    const float* __restrict__ data,
    const float* __restrict__ wih_f, const float* __restrict__ whh_f,
    const float* __restrict__ bih_f, const float* __restrict__ bhh_f,
    const float* __restrict__ wih_b, const float* __restrict__ whh_b,
    const float* __restrict__ bih_b, const float* __restrict__ bhh_b,
    float* __restrict__ x1f, float* __restrict__ x1b, float* __restrict__ out)
{
    extern __shared__ float sm[];
    const int tid = threadIdx.x;
    const int bid = blockIdx.x;
    const int dir = (bid >= 74) ? 1 : 0;
    const int cb  = (bid - dir * 74) * 14;

    const float* wih = dir ? wih_b : wih_f;
    const float* whh = dir ? whh_b : whh_f;
    const float* bih = dir ? bih_b : bih_f;
    const float* bhh = dir ? bhh_b : bhh_f;
    float* xout = dir ? x1b : x1f;
    const int outoff = dir ? 200 : 0;

    float* WP  = sm + R1_WP;
    float* WIH = sm + R1_WIH;
    float* BIH = sm + R1_BIH;
    float* BHH = sm + R1_BHH;
    float* HD  = sm + R1_HD;
    float* PG  = sm + R1_PG;
    float* XD  = sm + R1_XD;

    // WP flat idx = k2*600 + p*4 + c4 ; k = 2*k2+(c4>>1), j = 2*p+(c4&1)
    for (int i = tid; i < 30000; i += 640) {
        const int c4 = i & 3;
        const int p  = (i >> 2) % 150;
        const int k2 = i / 600;
        const int k  = 2 * k2 + (c4 >> 1);
        const int j  = 2 * p + (c4 & 1);
        WP[i] = whh[j * 100 + k];
    }
    for (int i = tid; i < 300; i += 640) {
        WIH[i] = wih[i]; BIH[i] = bih[i]; BHH[i] = bhh[i];
    }
    for (int i = tid; i < 2800; i += 640) HD[i] = 0.0f;
    for (int i = tid; i < 14 * 512; i += 640) {
        int c = i >> 9, s = i & 511;
        int b = cb + c;
        XD[i] = (b < BATCH) ? data[b * 512 + (dir ? (511 - s) : s)] : 0.0f;
    }

    // GEMM-thread constants
    int ks = 0, gg = 0, pp = 0;
    if (tid < 600) {
        ks = tid / 300;
        int rem = tid - 300 * ks;
        gg = rem / 150;
        pp = rem - 150 * gg;
    }
    // Activation item constants: it = tid + 640*j, j<3
    int  ac[3], au[3];
    bool av[3];
    long axo[3];  // xout flat offset at s=0 (advances by 100 per step)
    int  aoo[3];  // out flat offset
    #pragma unroll
    for (int j = 0; j < 3; j++) {
        const int it = tid + 640 * j;
        av[j] = false; ac[j] = 0; au[j] = 0; axo[j] = 0; aoo[j] = 0;
        if (it < 1400) {
            const int c = it / 100, u = it - 100 * (it / 100);
            const int b = cb + c;
            ac[j] = c; au[j] = u;
            if (b < BATCH) {
                av[j] = true;
                axo[j] = (long)b * 512 * 100 + u;
                aoo[j] = b * 400 + outoff + u;
            }
        }
    }
    __syncthreads();

    for (int s = 0; s < 512; s++) {
        if (tid < 600) {
            unsigned long long acc2[7];
            unsigned long long binit = 0ULL;
            if (ks == 0) {
                const float2 bb = *reinterpret_cast<const float2*>(BHH + 2 * pp);
                binit = pack2(bb.x, bb.y);
            }
            #pragma unroll
            for (int c = 0; c < 7; c++) acc2[c] = binit;
            const int kb = ks * 25;
            #pragma unroll 5
            for (int k2 = 0; k2 < 25; k2++) {
                const ulonglong2 wv = *reinterpret_cast<const ulonglong2*>(WP + ((kb + k2) * 150 + pp) * 4);
                #pragma unroll
                for (int c = 0; c < 7; c++) {
                    const ulonglong2 hv = *reinterpret_cast<const ulonglong2*>(HD + (gg * 7 + c) * 200 + 4 * (kb + k2));
                    fma2(acc2[c], hv.x, wv.x);
                    fma2(acc2[c], hv.y, wv.y);
                }
            }
            #pragma unroll
            for (int c = 0; c < 7; c++) {
                *reinterpret_cast<float2*>(PG + ks * 4200 + (gg * 7 + c) * 300 + 2 * pp) = unpack2(acc2[c]);
            }
        }
        __syncthreads();

        #pragma unroll
        for (int j = 0; j < 3; j++) {
            if (av[j]) {
                const int c = ac[j], u = au[j];
                const float xv  = XD[c * 512 + s];
                const float ir  = fmaf(xv, WIH[u],       BIH[u])       + PG[c * 300 + u]        + PG[4200 + c * 300 + u];
                const float iz  = fmaf(xv, WIH[100 + u], BIH[100 + u]) + PG[c * 300 + 100 + u]  + PG[4200 + c * 300 + 100 + u];
                const float inn = fmaf(xv, WIH[200 + u], BIH[200 + u]);
                const float hn  = PG[c * 300 + 200 + u] + PG[4200 + c * 300 + 200 + u];
                const float rg = sigf(ir);
                const float zg = sigf(iz);
                const float ng = tanh_fast(inn + rg * hn);
                const float hold = HD[(c * 100 + u) * 2];
                const float hnew = (1.0f - zg) * ng + zg * hold;
                *reinterpret_cast<float2*>(HD + (c * 100 + u) * 2) = make_float2(hnew, hnew);
                xout[axo[j] + (long)s * 100] = hnew;
                if (s == 511) out[aoo[j]] = hnew;
            }
        }
        __syncthreads();
    }
}

// =================================================================================
// Input-projection GEMM: out[M,150] = x[M,K] @ w[150,K]^T + bias.  M = 524288,
// K in {100, 50}. Block tile 128 x 160, 256 threads, 8 rows x 5 col-pairs of
// packed FFMA2 per thread. SMEM: duplicated X and paired W.
// =================================================================================
#define GM_SM_XDS 0        // 128*100 = 12800 (dup)
#define GM_SM_WPS 12800    // 25*80*4 = 8000
#define GM_SM_BS  20800    // 160
#define GM_SMEM_BYTES (20960 * 4)

__global__ void __launch_bounds__(256) gi_gemm_kernel(
    const float* __restrict__ x, const float* __restrict__ w,
    const float* __restrict__ bias, float* __restrict__ out, int K)
{
    extern __shared__ float sm[];
    float* XDS = sm + GM_SM_XDS;
    float* WPS = sm + GM_SM_WPS;
    float* BS  = sm + GM_SM_BS;
    const int tid = threadIdx.x;
    const int tx = tid & 15;
    const int ty = tid >> 4;
    const int m0 = blockIdx.x * 128;

    for (int i = tid; i < 160; i += 256) BS[i] = (i < 150) ? bias[i] : 0.0f;

    unsigned long long acc2[8][5];
    #pragma unroll
    for (int i = 0; i < 8; i++)
        #pragma unroll
        for (int j = 0; j < 5; j++) acc2[i][j] = 0ULL;

    const int nch = K / 50;
    for (int ch = 0; ch < nch; ch++) {
        const int k0 = ch * 50;
        __syncthreads();
        for (int i = tid; i < 128 * 50; i += 256) {
            const int r = i / 50, k = i - r * 50;
            const float v = x[(m0 + r) * K + k0 + k];
            *reinterpret_cast<float2*>(XDS + r * 100 + 2 * k) = make_float2(v, v);
        }
        for (int i = tid; i < 8000; i += 256) {
            const int c4 = i & 3;
            const int pp = (i >> 2) % 80;
            const int k2 = i / 320;
            const int k  = k0 + 2 * k2 + (c4 >> 1);
            const int n  = 2 * pp + (c4 & 1);
            WPS[i] = (n < 150) ? w[n * K + k] : 0.0f;
        }
        __syncthreads();
        for (int k2 = 0; k2 < 25; k2++) {
            ulonglong2 xx[8], ww[5];
            #pragma unroll
            for (int i = 0; i < 8; i++)
                xx[i] = *reinterpret_cast<const ulonglong2*>(XDS + (ty * 8 + i) * 100 + 4 * k2);
            #pragma unroll
            for (int j = 0; j < 5; j++)
                ww[j] = *reinterpret_cast<const ulonglong2*>(WPS + (k2 * 80 + tx + 16 * j) * 4);
            #pragma unroll
            for (int i = 0; i < 8; i++)
                #pragma unroll
                for (int j = 0; j < 5; j++) {
                    fma2(acc2[i][j], xx[i].x, ww[j].x);
                    fma2(acc2[i][j], xx[i].y, ww[j].y);
                }
        }
    }
    #pragma unroll
    for (int i = 0; i < 8; i++) {
        const int m = m0 + ty * 8 + i;
        #pragma unroll
        for (int j = 0; j < 5; j++) {
            const int pp = tx + 16 * j;
            if (pp < 75) {
                float2 v = unpack2(acc2[i][j]);
                v.x += BS[2 * pp];
                v.y += BS[2 * pp + 1];
                *reinterpret_cast<float2*>(out + m * 150 + 2 * pp) = v;
            }
        }
    }
}

// =================================================================================
// Layers 2/3 recurrence (H=50, gates=150, dilation 4 or 16). 28 chains/block,
// 320 threads, 2 blocks/SM -> 20 warps/SM. GEMM phase: 300 threads = 75 col-pairs
// x 4 chain-groups of 7. gi for the current step is PREFETCHED into registers
// before the GEMM phase so its GMEM latency hides behind the FFMA2 work.
// =================================================================================
#define R23_WP  0       // 25*75*4 = 7500
#define R23_BHH 7500    // 150 (+2 pad)
#define R23_HD  7652    // 28*50*2 = 2800 dup pairs (16B aligned)
#define R23_GH  10452   // 28*150 = 4200
#define R23_FLOATS 14652
#define R23_SMEM_BYTES (R23_FLOATS * 4)

__global__ void __launch_bounds__(320, 2) rec23_kernel(
    const float* __restrict__ gi_f, const float* __restrict__ gi_b,
    const float* __restrict__ whh_fp, const float* __restrict__ bhh_fp,
    const float* __restrict__ whh_bp, const float* __restrict__ bhh_bp,
    float* __restrict__ xout_f, float* __restrict__ xout_b,
    float* __restrict__ out, int offF, int offB,
    int dil, int ds, int nc, int bpd, int ctot)
{
    extern __shared__ float sm[];
    float* WP  = sm + R23_WP;
    float* BHH = sm + R23_BHH;
    float* HD  = sm + R23_HD;
    float* GH  = sm + R23_GH;
    const int tid = threadIdx.x;
    const int bid = blockIdx.x;
    const int dir = (bid >= bpd) ? 1 : 0;
    const int chain0 = (bid - dir * bpd) * 28;
    const float* gi  = dir ? gi_b : gi_f;
    const float* whh = dir ? whh_bp : whh_fp;
    const float* bhh = dir ? bhh_bp : bhh_fp;
    float* xout = dir ? xout_b : xout_f;
    const int outoff = dir ? offB : offF;

    // WP flat = k2*300 + p*4 + c4 ; k = 2k2+(c4>>1), j = 2p+(c4&1)
    for (int i = tid; i < 7500; i += 320) {
        const int c4 = i & 3;
        const int p  = (i >> 2) % 75;
        const int k2 = i / 300;
        const int k  = 2 * k2 + (c4 >> 1);
        const int j  = 2 * p + (c4 & 1);
        WP[i] = whh[j * 50 + k];
    }
    for (int i = tid; i < 150; i += 320) BHH[i] = bhh[i];
    for (int i = tid; i < 2800; i += 320) HD[i] = 0.0f;

    // GEMM-thread constants
    int gg = 0, pp = 0;
    if (tid < 300) { pp = tid % 75; gg = tid / 75; }

    // Activation item constants: it = tid + 320*j, j<5 (1400 items)
    int  ac[5], au[5], arr[5], aoo[5];
    bool av[5];
    long agi[5], axo[5];
    const long gstride = (long)dil * 150;
    const long xstride = (long)dil * 50;
    #pragma unroll
    for (int j = 0; j < 5; j++) {
        const int it = tid + 320 * j;
        av[j] = false; ac[j] = 0; au[j] = 0; arr[j] = 0; aoo[j] = 0; agi[j] = 0; axo[j] = 0;
        if (it < 1400) {
            const int c = it / 50, u = it - 50 * (it / 50);
            const int chain = chain0 + c;
            if (chain < ctot) {
                const int b  = chain >> ds;
                const int rr = chain & (dil - 1);
                av[j] = true; ac[j] = c; au[j] = u; arr[j] = rr;
                agi[j] = ((long)b * 512 + rr) * 150 + u;
                axo[j] = ((long)b * 512 + rr) * 50 + u;
                aoo[j] = b * 400 + outoff + u;
            }
        }
    }
    __syncthreads();

    for (int step = 0; step < nc; step++) {
        // ---- prefetch gi for this step (hidden behind the GEMM below) ----
        float pr[5], pz[5], pn[5];
        #pragma unroll
        for (int j = 0; j < 5; j++) {
            pr[j] = 0.0f; pz[j] = 0.0f; pn[j] = 0.0f;
            if (av[j]) {
                const float* gp = gi + agi[j] + (long)step * gstride;
                pr[j] = gp[0]; pz[j] = gp[50]; pn[j] = gp[100];
            }
        }

        if (tid < 300) {
            unsigned long long acc2[7];
            const float2 bb = *reinterpret_cast<const float2*>(BHH + 2 * pp);
            const unsigned long long binit = pack2(bb.x, bb.y);
            #pragma unroll
            for (int c = 0; c < 7; c++) acc2[c] = binit;
            #pragma unroll 5
            for (int k2 = 0; k2 < 25; k2++) {
                const ulonglong2 wv = *reinterpret_cast<const ulonglong2*>(WP + (k2 * 75 + pp) * 4);
                #pragma unroll
                for (int c = 0; c < 7; c++) {
                    const ulonglong2 hv = *reinterpret_cast<const ulonglong2*>(HD + (gg * 7 + c) * 100 + 4 * k2);
                    fma2(acc2[c], hv.x, wv.x);
                    fma2(acc2[c], hv.y, wv.y);
                }
            }
            #pragma unroll
            for (int c = 0; c < 7; c++) {
                *reinterpret_cast<float2*>(GH + (gg * 7 + c) * 150 + 2 * pp) = unpack2(acc2[c]);
            }
        }
        __syncthreads();

        #pragma unroll
        for (int j = 0; j < 5; j++) {
            if (av[j]) {
                const int c = ac[j], u = au[j];
                const float hr = GH[c * 150 + u];
                const float hz = GH[c * 150 + 50 + u];
                const float hn = GH[c * 150 + 100 + u];
                const float rg = sigf(pr[j] + hr);
                const float zg = sigf(pz[j] + hz);
                const float ng = tanh_fast(pn[j] + rg * hn);
                const float hold = HD[(c * 50 + u) * 2];
                const float hnew = (1.0f - zg) * ng + zg * hold;
                *reinterpret_cast<float2*>(HD + (c * 50 + u) * 2) = make_float2(hnew, hnew);
                if (xout) xout[axo[j] + (long)step * xstride] = hnew;
                if (step == nc - 1 && arr[j] == dil - 1) out[aoo[j]] = hnew;
            }
        }
        __syncthreads();
    }
}

// =================================================================================
// Host launcher
// =================================================================================
extern "C" void kernel_launch(void* const* d_in, const int* in_sizes, int n_in,
                              void* d_out, int out_size)
{
    const float* data = (const float*)d_in[0];
    const float* f1_wih = (const float*)d_in[1];
    const float* f1_whh = (const float*)d_in[2];
    const float* f1_bih = (const float*)d_in[3];
    const float* f1_bhh = (const float*)d_in[4];
    const float* f2_wih = (const float*)d_in[5];
    const float* f2_whh = (const float*)d_in[6];
    const float* f2_bih = (const float*)d_in[7];
    const float* f2_bhh = (const float*)d_in[8];
    const float* f3_wih = (const float*)d_in[9];
    const float* f3_whh = (const float*)d_in[10];
    const float* f3_bih = (const float*)d_in[11];
    const float* f3_bhh = (const float*)d_in[12];
    const float* b1_wih = (const float*)d_in[13];
    const float* b1_whh = (const float*)d_in[14];
    const float* b1_bih = (const float*)d_in[15];
    const float* b1_bhh = (const float*)d_in[16];
    const float* b2_wih = (const float*)d_in[17];
    const float* b2_whh = (const float*)d_in[18];
    const float* b2_bih = (const float*)d_in[19];
    const float* b2_bhh = (const float*)d_in[20];
    const float* b3_wih = (const float*)d_in[21];
    const float* b3_whh = (const float*)d_in[22];
    const float* b3_bih = (const float*)d_in[23];
    const float* b3_bhh = (const float*)d_in[24];
    float* out = (float*)d_out;

    float *x1f, *x1b, *gif, *gib, *x2f, *x2b;
    cudaGetSymbolAddress((void**)&x1f, g_x1f);
    cudaGetSymbolAddress((void**)&x1b, g_x1b);
    cudaGetSymbolAddress((void**)&gif, g_gif);
    cudaGetSymbolAddress((void**)&gib, g_gib);
    cudaGetSymbolAddress((void**)&x2f, g_x2f);
    cudaGetSymbolAddress((void**)&x2b, g_x2b);

    cudaFuncSetAttribute(rec1_kernel,    cudaFuncAttributeMaxDynamicSharedMemorySize, R1_SMEM_BYTES);
    cudaFuncSetAttribute(gi_gemm_kernel, cudaFuncAttributeMaxDynamicSharedMemorySize, GM_SMEM_BYTES);
    cudaFuncSetAttribute(rec23_kernel,   cudaFuncAttributeMaxDynamicSharedMemorySize, R23_SMEM_BYTES);

    // Layer 1 (dil=1): both directions in one wave of 148 persistent blocks.
    rec1_kernel<<<148, 640, R1_SMEM_BYTES>>>(
        data, f1_wih, f1_whh, f1_bih, f1_bhh,
        b1_wih, b1_whh, b1_bih, b1_bhh, x1f, x1b, out);

    // Layer 2 input projections: gi = x1 @ wih^T + bih   (K = 100)
    gi_gemm_kernel<<<MTOT / 128, 256, GM_SMEM_BYTES>>>(x1f, f2_wih, f2_bih, gif, 100);
    gi_gemm_kernel<<<MTOT / 128, 256, GM_SMEM_BYTES>>>(x1b, b2_wih, b2_bih, gib, 100);

    // Layer 2 recurrence (dil=4): 4096 chains/dir, 28/block -> bpd 147, grid 294.
    rec23_kernel<<<294, 320, R23_SMEM_BYTES>>>(
        gif, gib, f2_whh, f2_bhh, b2_whh, b2_bhh,
        x2f, x2b, out, 100, 300, 4, 2, 128, 147, 4096);

    // Layer 3 input projections (K = 50), reusing gi scratch.
    gi_gemm_kernel<<<MTOT / 128, 256, GM_SMEM_BYTES>>>(x2f, f3_wih, f3_bih, gif, 50);
    gi_gemm_kernel<<<MTOT / 128, 256, GM_SMEM_BYTES>>>(x2b, b3_wih, b3_bih, gib, 50);

    // Layer 3 recurrence (dil=16): 16384 chains/dir, 28/block -> bpd 586, grid 1172.
    rec23_kernel<<<1172, 320, R23_SMEM_BYTES>>>(
        gif, gib, f3_whh, f3_bhh, b3_whh, b3_bhh,
        nullptr, nullptr, out, 150, 350, 16, 4, 32, 586, 16384);

    (void)in_sizes; (void)n_in; (void)out_size;
}